// round 2
// baseline (speedup 1.0000x reference)
#include <cuda_runtime.h>
#include <math.h>

// Problem dims
#define B_  4
#define S_  1024
#define D_  1024
#define H_  512
#define N_  32
#define M_  (B_ * S_)    // 4096 rows
#define H2_ (2 * H_)     // 1024

// Scratch (allocation-free rule: __device__ globals)
__device__ float g_h[M_ * H2_];        // GELU(query@W1+b1): 16 MB
__device__ float g_c[B_ * N_ * H_];    // c[b,n,i] = sum_j hcm[b,n,(i+j)%H] * Wa[j]

// ---------------------------------------------------------------------------
// SGEMM: C[M,N] = A[M,K] @ B[K,N] + bias[N], optional exact GELU.
// 128x128 block tile, BK=8, 8x8 per thread, 256 threads. All dims % 128 == 0.
// ---------------------------------------------------------------------------
template <bool DO_GELU>
__global__ void sgemm_bias_act(const float* __restrict__ A,
                               const float* __restrict__ Bm,
                               const float* __restrict__ bias,
                               float* __restrict__ C,
                               int M, int N, int K) {
    constexpr int BM = 128, BN = 128, BK = 8, TM = 8, TN = 8;
    __shared__ float As[BK][BM];
    __shared__ float Bs[BK][BN];

    const int tid = threadIdx.x;
    const int bm = blockIdx.y, bn = blockIdx.x;

    // A tile load: 128 rows x 8 cols = 256 float4 (2 per row)
    const int aRow = tid >> 1;
    const int aCol = (tid & 1) * 4;
    // B tile load: 8 rows x 128 cols = 256 float4 (32 per row)
    const int bRow = tid >> 5;
    const int bCol = (tid & 31) * 4;
    // compute layout: 16x16 threads of 8x8 micro-tiles
    const int tr = (tid >> 4) * TM;
    const int tc = (tid & 15) * TN;

    const float* Aptr = A + (size_t)(bm * BM + aRow) * K + aCol;
    const float* Bptr = Bm + (size_t)bRow * N + (size_t)bn * BN + bCol;

    float acc[TM][TN] = {};
    float rM[TM], rN[TN];

    for (int k0 = 0; k0 < K; k0 += BK) {
        float4 av = *(const float4*)(Aptr + k0);
        As[aCol + 0][aRow] = av.x;
        As[aCol + 1][aRow] = av.y;
        As[aCol + 2][aRow] = av.z;
        As[aCol + 3][aRow] = av.w;
        *(float4*)&Bs[bRow][bCol] = *(const float4*)(Bptr + (size_t)k0 * N);
        __syncthreads();

#pragma unroll
        for (int k = 0; k < BK; k++) {
#pragma unroll
            for (int i = 0; i < TM; i += 4)
                *(float4*)&rM[i] = *(const float4*)&As[k][tr + i];
#pragma unroll
            for (int j = 0; j < TN; j += 4)
                *(float4*)&rN[j] = *(const float4*)&Bs[k][tc + j];
#pragma unroll
            for (int i = 0; i < TM; i++)
#pragma unroll
                for (int j = 0; j < TN; j++)
                    acc[i][j] = fmaf(rM[i], rN[j], acc[i][j]);
        }
        __syncthreads();
    }

#pragma unroll
    for (int i = 0; i < TM; i++) {
        float* Crow = C + (size_t)(bm * BM + tr + i) * N + (size_t)bn * BN + tc;
#pragma unroll
        for (int j = 0; j < TN; j += 4) {
            float4 bv = *(const float4*)&bias[bn * BN + tc + j];
            float4 v;
            v.x = acc[i][j + 0] + bv.x;
            v.y = acc[i][j + 1] + bv.y;
            v.z = acc[i][j + 2] + bv.z;
            v.w = acc[i][j + 3] + bv.w;
            if (DO_GELU) {
                v.x = 0.5f * v.x * (1.0f + erff(v.x * 0.70710678118654752f));
                v.y = 0.5f * v.y * (1.0f + erff(v.y * 0.70710678118654752f));
                v.z = 0.5f * v.z * (1.0f + erff(v.z * 0.70710678118654752f));
                v.w = 0.5f * v.w * (1.0f + erff(v.w * 0.70710678118654752f));
            }
            *(float4*)Crow = v;
            Crow += 4;
        }
    }
}

// ---------------------------------------------------------------------------
// Row-wise L2 normalize in place: keys[row,:] /= max(||row||, 1e-12)
// 1 block per row, 128 threads, float4 each.
// ---------------------------------------------------------------------------
__global__ void normalize_rows(float* __restrict__ keys) {
    const int row = blockIdx.x;
    const int t = threadIdx.x;
    float4* p = (float4*)(keys + (size_t)row * H_);
    float4 v = p[t];
    float ss = v.x * v.x + v.y * v.y + v.z * v.z + v.w * v.w;
#pragma unroll
    for (int o = 16; o; o >>= 1) ss += __shfl_xor_sync(0xffffffffu, ss, o);
    __shared__ float ws[4];
    if ((t & 31) == 0) ws[t >> 5] = ss;
    __syncthreads();
    float tot = ws[0] + ws[1] + ws[2] + ws[3];
    float inv = 1.0f / fmaxf(sqrtf(tot), 1e-12f);
    v.x *= inv; v.y *= inv; v.z *= inv; v.w *= inv;
    p[t] = v;
}

// ---------------------------------------------------------------------------
// c[b,n,i] = sum_j hcm[b,n,(i+j)%H] * Wa[j]
// 1 block per (b,n) = 128 blocks, 128 threads, 4 outputs/thread (sliding win).
// ---------------------------------------------------------------------------
__global__ void compute_c_kernel(const float* __restrict__ hcm,
                                 const float* __restrict__ Wa,
                                 float* __restrict__ c) {
    __shared__ __align__(16) float hs[1024];   // hcm row duplicated
    __shared__ __align__(16) float was[512];
    const int bn = blockIdx.x;
    const int t = threadIdx.x;
#pragma unroll
    for (int r = 0; r < 4; r++) {
        int j = t + 128 * r;
        float v = hcm[(size_t)bn * H_ + j];
        hs[j] = v;
        hs[j + 512] = v;
        was[j] = Wa[j];
    }
    __syncthreads();

    const int h0 = 4 * t;
    float4 a = {0.f, 0.f, 0.f, 0.f};
    float4 mw = *(const float4*)&hs[h0];
#pragma unroll 4
    for (int i = 0; i < 512; i += 4) {
        float4 kv = *(const float4*)&was[i];
        float4 mn = *(const float4*)&hs[i + 4 + h0];
        a.x = fmaf(kv.x, mw.x, a.x); a.y = fmaf(kv.x, mw.y, a.y); a.z = fmaf(kv.x, mw.z, a.z); a.w = fmaf(kv.x, mw.w, a.w);
        a.x = fmaf(kv.y, mw.y, a.x); a.y = fmaf(kv.y, mw.z, a.y); a.z = fmaf(kv.y, mw.w, a.z); a.w = fmaf(kv.y, mn.x, a.w);
        a.x = fmaf(kv.z, mw.z, a.x); a.y = fmaf(kv.z, mw.w, a.y); a.z = fmaf(kv.z, mn.x, a.z); a.w = fmaf(kv.z, mn.y, a.w);
        a.x = fmaf(kv.w, mw.w, a.x); a.y = fmaf(kv.w, mn.x, a.y); a.z = fmaf(kv.w, mn.y, a.z); a.w = fmaf(kv.w, mn.z, a.w);
        mw = mn;
    }
    *(float4*)&c[(size_t)bn * H_ + h0] = a;
}

// ---------------------------------------------------------------------------
// Fused slot attention per (b,s) row:
//   scores[n] = keys . c[b,n] + ba   -> softmax over N=32 -> w
//   m[:] = sum_n w[n] * hcm[b,n,:]
//   context[h] = sum_i keys[i] * m[(i+h)%H]   (circular correlation)
// 1 block per row (4096 blocks), 128 threads.
// ---------------------------------------------------------------------------
__global__ __launch_bounds__(128)
void attention_kernel(const float* __restrict__ keys,
                      const float* __restrict__ c,
                      const float* __restrict__ hcm,
                      const float* __restrict__ ba,
                      float* __restrict__ context) {
    __shared__ __align__(16) float ks[512];
    __shared__ __align__(16) float ms[1024];
    __shared__ float sc[32];
    __shared__ float wt[32];

    const int row = blockIdx.x;        // b*S + s
    const int b = row >> 10;
    const int t = threadIdx.x;

    ((float4*)ks)[t] = ((const float4*)(keys + (size_t)row * H_))[t];
    __syncthreads();

    // scores: 32 slots x 4 lanes each
    {
        const int n = t >> 2, l = t & 3;
        const float4* c4 = (const float4*)(c + ((size_t)(b * N_ + n)) * H_);
        const float4* k4 = (const float4*)ks;
        float p = 0.f;
#pragma unroll 4
        for (int i = l; i < 128; i += 4) {
            float4 cv = c4[i], kv = k4[i];
            p += cv.x * kv.x + cv.y * kv.y + cv.z * kv.z + cv.w * kv.w;
        }
        p += __shfl_xor_sync(0xffffffffu, p, 1);
        p += __shfl_xor_sync(0xffffffffu, p, 2);
        if (l == 0) sc[n] = p + ba[0];
    }
    __syncthreads();

    // softmax over 32 slots in warp 0
    if (t < 32) {
        float v = sc[t];
        float mx = v;
#pragma unroll
        for (int o = 16; o; o >>= 1) mx = fmaxf(mx, __shfl_xor_sync(0xffffffffu, mx, o));
        float e = expf(v - mx);
        float sm = e;
#pragma unroll
        for (int o = 16; o; o >>= 1) sm += __shfl_xor_sync(0xffffffffu, sm, o);
        wt[t] = e / sm;
    }
    __syncthreads();

    // m = sum_n w[n] * hcm[b,n,:]  (duplicated for circular window)
#pragma unroll
    for (int r = 0; r < 4; r++) {
        int j = t + 128 * r;
        float a = 0.f;
#pragma unroll 8
        for (int n = 0; n < 32; n++)
            a = fmaf(wt[n], hcm[((size_t)b * N_ + n) * H_ + j], a);
        ms[j] = a;
        ms[j + 512] = a;
    }
    __syncthreads();

    // circular correlation: 4 outputs per thread, sliding float4 window
    const int h0 = 4 * t;
    float4 a4 = {0.f, 0.f, 0.f, 0.f};
    float4 mw = *(const float4*)&ms[h0];
    const float4* k4 = (const float4*)ks;
#pragma unroll 4
    for (int i = 0; i < 512; i += 4) {
        float4 kv = k4[i >> 2];
        float4 mn = *(const float4*)&ms[i + 4 + h0];
        a4.x = fmaf(kv.x, mw.x, a4.x); a4.y = fmaf(kv.x, mw.y, a4.y); a4.z = fmaf(kv.x, mw.z, a4.z); a4.w = fmaf(kv.x, mw.w, a4.w);
        a4.x = fmaf(kv.y, mw.y, a4.x); a4.y = fmaf(kv.y, mw.z, a4.y); a4.z = fmaf(kv.y, mw.w, a4.z); a4.w = fmaf(kv.y, mn.x, a4.w);
        a4.x = fmaf(kv.z, mw.z, a4.x); a4.y = fmaf(kv.z, mw.w, a4.y); a4.z = fmaf(kv.z, mn.x, a4.z); a4.w = fmaf(kv.z, mn.y, a4.w);
        a4.x = fmaf(kv.w, mw.w, a4.x); a4.y = fmaf(kv.w, mn.x, a4.y); a4.z = fmaf(kv.w, mn.y, a4.z); a4.w = fmaf(kv.w, mn.z, a4.w);
        mw = mn;
    }
    *(float4*)(context + (size_t)row * H_ + h0) = a4;
}

// ---------------------------------------------------------------------------
// Launch
// ---------------------------------------------------------------------------
extern "C" void kernel_launch(void* const* d_in, const int* in_sizes, int n_in,
                              void* d_out, int out_size) {
    const float* query = (const float*)d_in[0];  // [B,S,D]
    const float* hcm   = (const float*)d_in[1];  // [B,N,H]
    const float* W1    = (const float*)d_in[2];  // [D,2H]
    const float* b1    = (const float*)d_in[3];  // [2H]
    const float* W2    = (const float*)d_in[4];  // [2H,H]
    const float* b2    = (const float*)d_in[5];  // [H]
    const float* Wa    = (const float*)d_in[6];  // [H,1]
    const float* ba    = (const float*)d_in[7];  // [1]

    float* out = (float*)d_out;
    float* context = out;                          // [B,S,H]
    float* keys    = out + (size_t)M_ * H_;        // [B,S,H]

    float* hbuf;
    cudaGetSymbolAddress((void**)&hbuf, g_h);
    float* cbuf;
    cudaGetSymbolAddress((void**)&cbuf, g_c);

    // 1) h = GELU(query @ W1 + b1)  [4096,1024]
    {
        dim3 grid(H2_ / 128, M_ / 128);
        sgemm_bias_act<true><<<grid, 256>>>(query, W1, b1, hbuf, M_, H2_, D_);
    }
    // 2) keys_raw = h @ W2 + b2     [4096,512]
    {
        dim3 grid(H_ / 128, M_ / 128);
        sgemm_bias_act<false><<<grid, 256>>>(hbuf, W2, b2, keys, M_, H_, H2_);
    }
    // 3) L2-normalize keys in place
    normalize_rows<<<M_, 128>>>(keys);
    // 4) c[b,n,:] = circ-corr(hcm[b,n,:], Wa)
    compute_c_kernel<<<B_ * N_, 128>>>(hcm, Wa, cbuf);
    // 5) fused scores/softmax/mixture/correlation -> context
    attention_kernel<<<M_, 128>>>(keys, cbuf, hcm, ba, context);
}

// round 4
// speedup vs baseline: 2.1853x; 2.1853x over previous
#include <cuda_runtime.h>
#include <cuda_bf16.h>
#include <math.h>
#include <stdint.h>

// Problem dims
#define B_  4
#define S_  1024
#define D_  1024
#define H_  512
#define N_  32
#define M_  (B_ * S_)    // 4096
#define H2_ (2 * H_)     // 1024

// ---------------------------------------------------------------------------
// Scratch (__device__ globals; no allocs allowed)
// ---------------------------------------------------------------------------
__device__ __nv_bfloat16 g_qh[M_ * D_],  g_ql[M_ * D_];     // query split [4096,1024]
__device__ __nv_bfloat16 g_hh[M_ * H2_], g_hl[M_ * H2_];    // GELU(h) split [4096,1024]
__device__ __nv_bfloat16 g_w1h[D_ * H2_], g_w1l[D_ * H2_];  // W1 split [1024,1024] (K-major, native)
__device__ __nv_bfloat16 g_w2h[H2_ * H_], g_w2l[H2_ * H_];  // W2 split [1024,512]
__device__ float g_c[B_ * N_ * H_];

// ---------------------------------------------------------------------------
// PTX helpers (sm_80-era only: mma.sync / ldmatrix / cp.async)
// ---------------------------------------------------------------------------
__device__ __forceinline__ uint32_t smem_u32(const void* p) {
    uint32_t a;
    asm("{ .reg .u64 t; cvta.to.shared.u64 t, %1; cvt.u32.u64 %0, t; }" : "=r"(a) : "l"(p));
    return a;
}

__device__ __forceinline__ void ldsm_x4(uint32_t& r0, uint32_t& r1, uint32_t& r2, uint32_t& r3,
                                        uint32_t addr) {
    asm volatile("ldmatrix.sync.aligned.m8n8.x4.shared.b16 {%0,%1,%2,%3}, [%4];"
                 : "=r"(r0), "=r"(r1), "=r"(r2), "=r"(r3) : "r"(addr));
}
__device__ __forceinline__ void ldsm_x4t(uint32_t& r0, uint32_t& r1, uint32_t& r2, uint32_t& r3,
                                         uint32_t addr) {
    asm volatile("ldmatrix.sync.aligned.m8n8.x4.trans.shared.b16 {%0,%1,%2,%3}, [%4];"
                 : "=r"(r0), "=r"(r1), "=r"(r2), "=r"(r3) : "r"(addr));
}
__device__ __forceinline__ void mma_bf16(float* d, uint32_t a0, uint32_t a1, uint32_t a2,
                                         uint32_t a3, uint32_t b0, uint32_t b1) {
    asm volatile(
        "mma.sync.aligned.m16n8k16.row.col.f32.bf16.bf16.f32 "
        "{%0,%1,%2,%3}, {%4,%5,%6,%7}, {%8,%9}, {%0,%1,%2,%3};"
        : "+f"(d[0]), "+f"(d[1]), "+f"(d[2]), "+f"(d[3])
        : "r"(a0), "r"(a1), "r"(a2), "r"(a3), "r"(b0), "r"(b1));
}
__device__ __forceinline__ void cp16(uint32_t smem_addr, const void* gptr) {
    asm volatile("cp.async.cg.shared.global [%0], [%1], 16;" :: "r"(smem_addr), "l"(gptr));
}
#define CP_COMMIT() asm volatile("cp.async.commit_group;" ::: "memory")
#define CP_WAIT1()  asm volatile("cp.async.wait_group 1;" ::: "memory")
#define CP_WAIT0()  asm volatile("cp.async.wait_group 0;" ::: "memory")

// ---------------------------------------------------------------------------
// Prep: elementwise fp32 -> bf16 hi/lo split (vectorized float4)
// ---------------------------------------------------------------------------
__global__ void split_fp32(const float* __restrict__ src,
                           __nv_bfloat16* __restrict__ dh,
                           __nv_bfloat16* __restrict__ dl, int n4) {
    int i = blockIdx.x * blockDim.x + threadIdx.x;
    if (i >= n4) return;
    float4 v = ((const float4*)src)[i];
    float vv[4] = {v.x, v.y, v.z, v.w};
    uint32_t hh[4], ll[4];
#pragma unroll
    for (int q = 0; q < 4; q++) {
        __nv_bfloat16 h = __float2bfloat16(vv[q]);
        __nv_bfloat16 l = __float2bfloat16(vv[q] - __bfloat162float(h));
        hh[q] = __bfloat16_as_ushort(h);
        ll[q] = __bfloat16_as_ushort(l);
    }
    uint2 ph, pl;
    ph.x = hh[0] | (hh[1] << 16); ph.y = hh[2] | (hh[3] << 16);
    pl.x = ll[0] | (ll[1] << 16); pl.y = ll[2] | (ll[3] << 16);
    ((uint2*)dh)[i] = ph;
    ((uint2*)dl)[i] = pl;
}

// ---------------------------------------------------------------------------
// Tensor-core GEMM (mma.sync bf16, 3-term hi/lo): C = A @ B + bias
//   A: split bf16 [Mtot, K] row-major (hi, lo)
//   B: split bf16 [K, Ntot] row-major (hi, lo)
// Tile 128x128, BK=64, 8 warps (2x4 -> warp tile 64x32), 2-stage cp.async.
// MODE 0: GELU(acc+bias) -> split bf16 (outH/outL).  MODE 1: acc+bias -> fp32.
// smem stage layout (64KB): Ah[128][64] +0 | Al +16K | Bh[64][128] +32K | Bl +48K
// swizzle: 16B-unit u at row r -> A: u^(r&7); B: (u&8)|((u^r)&7)
// ---------------------------------------------------------------------------
template <int MODE>
__global__ void __launch_bounds__(256, 1)
gemm_mma(const __nv_bfloat16* __restrict__ Ah, const __nv_bfloat16* __restrict__ Al,
         const __nv_bfloat16* __restrict__ Bh, const __nv_bfloat16* __restrict__ Bl,
         const float* __restrict__ bias,
         float* __restrict__ outF,
         __nv_bfloat16* __restrict__ outH, __nv_bfloat16* __restrict__ outL,
         int Ntot, int Ktot) {
    extern __shared__ char smp[];
    const uint32_t sb = smem_u32(smp);
    const int tid = threadIdx.x;
    const int wid = tid >> 5, lane = tid & 31;
    const int wm = wid >> 2, wn = wid & 3;           // 2 x 4 warp grid
    const int m_warp = wm * 64, n_warp = wn * 32;
    const int m0 = blockIdx.y * 128, n0 = blockIdx.x * 128;
    const int gid = lane >> 2, tig = lane & 3;

    // ---- stage loader (cp.async, swizzled) ----
    auto load_stage = [&](int c, int buf) {
        const uint32_t bb = sb + (uint32_t)buf * 65536u;
        const int k0 = c * 64;
        // A: 128 rows x 8 units (hi+lo)
#pragma unroll
        for (int j = 0; j < 4; j++) {
            int g = tid + 256 * j;
            int r = g >> 3, u = g & 7;
            size_t so = (size_t)(m0 + r) * Ktot + k0 + u * 8;
            uint32_t sw = (uint32_t)(r * 128 + ((u ^ (r & 7)) << 4));
            cp16(bb + sw, Ah + so);
            cp16(bb + 16384 + sw, Al + so);
        }
        // B: 64 rows x 16 units (hi+lo)
#pragma unroll
        for (int j = 0; j < 4; j++) {
            int g = tid + 256 * j;
            int r = g >> 4, u = g & 15;
            size_t so = (size_t)(k0 + r) * Ntot + n0 + u * 8;
            uint32_t sw = (uint32_t)(r * 256 + (((u & 8) | ((u ^ r) & 7)) << 4));
            cp16(bb + 32768 + sw, Bh + so);
            cp16(bb + 49152 + sw, Bl + so);
        }
    };

    float acc[4][4][4] = {};   // [m16 tile][n8 tile][regs]

    const int NK = Ktot / 64;
    load_stage(0, 0);
    CP_COMMIT();

    for (int c = 0; c < NK; c++) {
        if (c + 1 < NK) { load_stage(c + 1, (c + 1) & 1); CP_COMMIT(); CP_WAIT1(); }
        else           { CP_WAIT0(); }
        __syncthreads();

        const uint32_t bb = sb + (uint32_t)(c & 1) * 65536u;
#pragma unroll
        for (int s = 0; s < 4; s++) {            // 4 k16 steps in this stage
            // B fragments: 2 n16-tiles, hi+lo
            uint32_t bh[2][4], bl[2][4];
            {
                const int kr = s * 16 + (lane & 7) + (lane & 8);
                const uint32_t swk = (uint32_t)(kr * 256);
#pragma unroll
                for (int nt = 0; nt < 2; nt++) {
                    int un = (n_warp >> 3) + nt * 2 + (lane >> 4);
                    uint32_t sw = swk + (uint32_t)((((un & 8) | ((un ^ kr) & 7)) << 4));
                    ldsm_x4t(bh[nt][0], bh[nt][1], bh[nt][2], bh[nt][3], bb + 32768 + sw);
                    ldsm_x4t(bl[nt][0], bl[nt][1], bl[nt][2], bl[nt][3], bb + 49152 + sw);
                }
            }
            // A fragments + MMAs per m16 tile
            const int ar = m_warp + (lane & 15);
            const int au = s * 2 + (lane >> 4);
#pragma unroll
            for (int mt = 0; mt < 4; mt++) {
                const int r = ar + mt * 16;
                uint32_t sw = (uint32_t)(r * 128 + ((au ^ (r & 7)) << 4));
                uint32_t ah0, ah1, ah2, ah3, al0, al1, al2, al3;
                ldsm_x4(ah0, ah1, ah2, ah3, bb + sw);
                ldsm_x4(al0, al1, al2, al3, bb + 16384 + sw);
#pragma unroll
                for (int nb = 0; nb < 4; nb++) {
                    const int nt = nb >> 1, hf = (nb & 1) * 2;
                    mma_bf16(acc[mt][nb], ah0, ah1, ah2, ah3, bh[nt][hf], bh[nt][hf + 1]);
                    mma_bf16(acc[mt][nb], ah0, ah1, ah2, ah3, bl[nt][hf], bl[nt][hf + 1]);
                    mma_bf16(acc[mt][nb], al0, al1, al2, al3, bh[nt][hf], bh[nt][hf + 1]);
                }
            }
        }
        __syncthreads();
    }

    // ---- epilogue ----
#pragma unroll
    for (int mt = 0; mt < 4; mt++) {
        const int r0 = m0 + m_warp + mt * 16 + gid;
#pragma unroll
        for (int j = 0; j < 4; j++) {
            const int col = n0 + n_warp + j * 8 + tig * 2;
            float2 bv = *(const float2*)&bias[col];
            float v[4];
            v[0] = acc[mt][j][0] + bv.x; v[1] = acc[mt][j][1] + bv.y;
            v[2] = acc[mt][j][2] + bv.x; v[3] = acc[mt][j][3] + bv.y;
            if (MODE == 0) {
#pragma unroll
                for (int q = 0; q < 4; q++)
                    v[q] = 0.5f * v[q] * (1.0f + erff(v[q] * 0.70710678118654752f));
#pragma unroll
                for (int half = 0; half < 2; half++) {
                    const int rr = r0 + half * 8;
                    float a = v[half * 2], b = v[half * 2 + 1];
                    __nv_bfloat16 h0 = __float2bfloat16(a);
                    __nv_bfloat16 h1 = __float2bfloat16(b);
                    __nv_bfloat16 l0 = __float2bfloat16(a - __bfloat162float(h0));
                    __nv_bfloat16 l1 = __float2bfloat16(b - __bfloat162float(h1));
                    uint32_t ph = (uint32_t)__bfloat16_as_ushort(h0) | ((uint32_t)__bfloat16_as_ushort(h1) << 16);
                    uint32_t pl = (uint32_t)__bfloat16_as_ushort(l0) | ((uint32_t)__bfloat16_as_ushort(l1) << 16);
                    *(uint32_t*)(outH + (size_t)rr * Ntot + col) = ph;
                    *(uint32_t*)(outL + (size_t)rr * Ntot + col) = pl;
                }
            } else {
                *(float2*)(outF + (size_t)r0 * Ntot + col) = make_float2(v[0], v[1]);
                *(float2*)(outF + (size_t)(r0 + 8) * Ntot + col) = make_float2(v[2], v[3]);
            }
        }
    }
}

// ---------------------------------------------------------------------------
// Row-wise L2 normalize in place
// ---------------------------------------------------------------------------
__global__ void normalize_rows(float* __restrict__ keys) {
    const int row = blockIdx.x;
    const int t = threadIdx.x;
    float4* p = (float4*)(keys + (size_t)row * H_);
    float4 v = p[t];
    float ss = v.x * v.x + v.y * v.y + v.z * v.z + v.w * v.w;
#pragma unroll
    for (int o = 16; o; o >>= 1) ss += __shfl_xor_sync(0xffffffffu, ss, o);
    __shared__ float ws[4];
    if ((t & 31) == 0) ws[t >> 5] = ss;
    __syncthreads();
    float tot = ws[0] + ws[1] + ws[2] + ws[3];
    float inv = 1.0f / fmaxf(sqrtf(tot), 1e-12f);
    v.x *= inv; v.y *= inv; v.z *= inv; v.w *= inv;
    p[t] = v;
}

// ---------------------------------------------------------------------------
// c[b,n,i] = sum_j hcm[b,n,(i+j)%H] * Wa[j]
// ---------------------------------------------------------------------------
__global__ void compute_c_kernel(const float* __restrict__ hcm,
                                 const float* __restrict__ Wa,
                                 float* __restrict__ c) {
    __shared__ __align__(16) float hs[1024];
    __shared__ __align__(16) float was[512];
    const int bn = blockIdx.x;
    const int t = threadIdx.x;
#pragma unroll
    for (int r = 0; r < 4; r++) {
        int j = t + 128 * r;
        float v = hcm[(size_t)bn * H_ + j];
        hs[j] = v; hs[j + 512] = v;
        was[j] = Wa[j];
    }
    __syncthreads();
    const int h0 = 4 * t;
    float4 a = {0.f, 0.f, 0.f, 0.f};
    float4 mw = *(const float4*)&hs[h0];
#pragma unroll 4
    for (int i = 0; i < 512; i += 4) {
        float4 kv = *(const float4*)&was[i];
        float4 mn = *(const float4*)&hs[i + 4 + h0];
        a.x = fmaf(kv.x, mw.x, a.x); a.y = fmaf(kv.x, mw.y, a.y); a.z = fmaf(kv.x, mw.z, a.z); a.w = fmaf(kv.x, mw.w, a.w);
        a.x = fmaf(kv.y, mw.y, a.x); a.y = fmaf(kv.y, mw.z, a.y); a.z = fmaf(kv.y, mw.w, a.z); a.w = fmaf(kv.y, mn.x, a.w);
        a.x = fmaf(kv.z, mw.z, a.x); a.y = fmaf(kv.z, mw.w, a.y); a.z = fmaf(kv.z, mn.x, a.z); a.w = fmaf(kv.z, mn.y, a.w);
        a.x = fmaf(kv.w, mw.w, a.x); a.y = fmaf(kv.w, mn.x, a.y); a.z = fmaf(kv.w, mn.y, a.z); a.w = fmaf(kv.w, mn.z, a.w);
        mw = mn;
    }
    *(float4*)&c[(size_t)bn * H_ + h0] = a;
}

// ---------------------------------------------------------------------------
// Fused slot attention per (b,s) row (proven round-2 version)
// ---------------------------------------------------------------------------
__global__ __launch_bounds__(128)
void attention_kernel(const float* __restrict__ keys,
                      const float* __restrict__ c,
                      const float* __restrict__ hcm,
                      const float* __restrict__ ba,
                      float* __restrict__ context) {
    __shared__ __align__(16) float ks[512];
    __shared__ __align__(16) float ms[1024];
    __shared__ float sc[32];
    __shared__ float wt[32];

    const int row = blockIdx.x;
    const int b = row >> 10;
    const int t = threadIdx.x;

    ((float4*)ks)[t] = ((const float4*)(keys + (size_t)row * H_))[t];
    __syncthreads();

    {
        const int n = t >> 2, l = t & 3;
        const float4* c4 = (const float4*)(c + ((size_t)(b * N_ + n)) * H_);
        const float4* k4 = (const float4*)ks;
        float p = 0.f;
#pragma unroll 4
        for (int i = l; i < 128; i += 4) {
            float4 cv = c4[i], kv = k4[i];
            p += cv.x * kv.x + cv.y * kv.y + cv.z * kv.z + cv.w * kv.w;
        }
        p += __shfl_xor_sync(0xffffffffu, p, 1);
        p += __shfl_xor_sync(0xffffffffu, p, 2);
        if (l == 0) sc[n] = p + ba[0];
    }
    __syncthreads();

    if (t < 32) {
        float v = sc[t];
        float mx = v;
#pragma unroll
        for (int o = 16; o; o >>= 1) mx = fmaxf(mx, __shfl_xor_sync(0xffffffffu, mx, o));
        float e = expf(v - mx);
        float sm = e;
#pragma unroll
        for (int o = 16; o; o >>= 1) sm += __shfl_xor_sync(0xffffffffu, sm, o);
        wt[t] = e / sm;
    }
    __syncthreads();

#pragma unroll
    for (int r = 0; r < 4; r++) {
        int j = t + 128 * r;
        float a = 0.f;
#pragma unroll 8
        for (int n = 0; n < 32; n++)
            a = fmaf(wt[n], hcm[((size_t)b * N_ + n) * H_ + j], a);
        ms[j] = a;
        ms[j + 512] = a;
    }
    __syncthreads();

    const int h0 = 4 * t;
    float4 a4 = {0.f, 0.f, 0.f, 0.f};
    float4 mw = *(const float4*)&ms[h0];
    const float4* k4 = (const float4*)ks;
#pragma unroll 4
    for (int i = 0; i < 512; i += 4) {
        float4 kv = k4[i >> 2];
        float4 mn = *(const float4*)&ms[i + 4 + h0];
        a4.x = fmaf(kv.x, mw.x, a4.x); a4.y = fmaf(kv.x, mw.y, a4.y); a4.z = fmaf(kv.x, mw.z, a4.z); a4.w = fmaf(kv.x, mw.w, a4.w);
        a4.x = fmaf(kv.y, mw.y, a4.x); a4.y = fmaf(kv.y, mw.z, a4.y); a4.z = fmaf(kv.y, mw.w, a4.z); a4.w = fmaf(kv.y, mn.x, a4.w);
        a4.x = fmaf(kv.z, mw.z, a4.x); a4.y = fmaf(kv.z, mw.w, a4.y); a4.z = fmaf(kv.z, mn.x, a4.z); a4.w = fmaf(kv.z, mn.y, a4.w);
        a4.x = fmaf(kv.w, mw.w, a4.x); a4.y = fmaf(kv.w, mn.x, a4.y); a4.z = fmaf(kv.w, mn.y, a4.z); a4.w = fmaf(kv.w, mn.z, a4.w);
        mw = mn;
    }
    *(float4*)(context + (size_t)row * H_ + h0) = a4;
}

// ---------------------------------------------------------------------------
// Launch
// ---------------------------------------------------------------------------
extern "C" void kernel_launch(void* const* d_in, const int* in_sizes, int n_in,
                              void* d_out, int out_size) {
    const float* query = (const float*)d_in[0];
    const float* hcm   = (const float*)d_in[1];
    const float* W1    = (const float*)d_in[2];
    const float* b1    = (const float*)d_in[3];
    const float* W2    = (const float*)d_in[4];
    const float* b2    = (const float*)d_in[5];
    const float* Wa    = (const float*)d_in[6];
    const float* ba    = (const float*)d_in[7];

    float* out = (float*)d_out;
    float* context = out;
    float* keys    = out + (size_t)M_ * H_;

    __nv_bfloat16 *qh, *ql, *hh, *hl, *w1h, *w1l, *w2h, *w2l;
    float* cbuf;
    cudaGetSymbolAddress((void**)&qh, g_qh);
    cudaGetSymbolAddress((void**)&ql, g_ql);
    cudaGetSymbolAddress((void**)&hh, g_hh);
    cudaGetSymbolAddress((void**)&hl, g_hl);
    cudaGetSymbolAddress((void**)&w1h, g_w1h);
    cudaGetSymbolAddress((void**)&w1l, g_w1l);
    cudaGetSymbolAddress((void**)&w2h, g_w2h);
    cudaGetSymbolAddress((void**)&w2l, g_w2l);
    cudaGetSymbolAddress((void**)&cbuf, g_c);

    const int SMEM_BYTES = 131072;
    cudaFuncSetAttribute(gemm_mma<0>, cudaFuncAttributeMaxDynamicSharedMemorySize, SMEM_BYTES);
    cudaFuncSetAttribute(gemm_mma<1>, cudaFuncAttributeMaxDynamicSharedMemorySize, SMEM_BYTES);

    // prep: hi/lo splits (no transposes needed; B consumed [K][N] row-major)
    split_fp32<<<(M_ * D_ / 4 + 255) / 256, 256>>>(query, qh, ql, M_ * D_ / 4);
    split_fp32<<<(D_ * H2_ / 4 + 255) / 256, 256>>>(W1, w1h, w1l, D_ * H2_ / 4);
    split_fp32<<<(H2_ * H_ / 4 + 255) / 256, 256>>>(W2, w2h, w2l, H2_ * H_ / 4);
    compute_c_kernel<<<B_ * N_, 128>>>(hcm, Wa, cbuf);

    // GEMM1: h = GELU(query@W1+b1), written split-bf16
    gemm_mma<0><<<dim3(H2_ / 128, M_ / 128), 256, SMEM_BYTES>>>(
        qh, ql, w1h, w1l, b1, nullptr, hh, hl, H2_, D_);
    // GEMM2: keys = h@W2+b2 (fp32)
    gemm_mma<1><<<dim3(H_ / 128, M_ / 128), 256, SMEM_BYTES>>>(
        hh, hl, w2h, w2l, b2, keys, nullptr, nullptr, H_, H2_);

    normalize_rows<<<M_, 128>>>(keys);
    attention_kernel<<<M_, 128>>>(keys, cbuf, hcm, ba, context);
}